// round 11
// baseline (speedup 1.0000x reference)
#include <cuda_runtime.h>
#include <cuda_fp16.h>
#include <cstdint>

// Problem constants
#define BATCH 8
#define NPIX  4096          // 64*64
#define CIN   256
#define DHEAD 32
#define MROWS (BATCH*NPIX)  // 32768

#define QT 128              // q rows per attn block (8 warps x 16 rows)
#define MT 64               // k/v rows per inner tile

// smem strides (in halves). 40 halves = 80B rows: 16B aligned.
#define TS 40
#define WQS 104
#define WOS 136

#define LOG2E 1.4426950408889634f

// fp16 scratch (device globals; no runtime allocation allowed)
__device__ __half g_q[MROWS * DHEAD];
__device__ __half g_k[MROWS * DHEAD];
__device__ __half g_v[MROWS * DHEAD];
__device__ __half g_attn[MROWS * DHEAD];

// ---------------------------------------------------------------------------
// helpers
// ---------------------------------------------------------------------------
__device__ __forceinline__ uint32_t pack2(float lo, float hi) {
    __half2 h = __floats2half2_rn(lo, hi);
    return *reinterpret_cast<uint32_t*>(&h);
}
__device__ __forceinline__ uint32_t h2exp2(uint32_t u) {
    uint32_t r;
    asm("ex2.approx.f16x2 %0, %1;" : "=r"(r) : "r"(u));
    return r;
}
__device__ __forceinline__ uint32_t hadd2u(uint32_t a, uint32_t b) {
    __half2 r = __hadd2(*reinterpret_cast<__half2*>(&a),
                        *reinterpret_cast<__half2*>(&b));
    return *reinterpret_cast<uint32_t*>(&r);
}
__device__ __forceinline__ float hsum2f(uint32_t a) {
    float2 f = __half22float2(*reinterpret_cast<__half2*>(&a));
    return f.x + f.y;
}

__device__ __forceinline__ void mma_f16(float* d, const uint32_t* a,
                                        uint32_t b0, uint32_t b1, const float* c)
{
    asm("mma.sync.aligned.m16n8k16.row.col.f32.f16.f16.f32 "
        "{%0,%1,%2,%3}, {%4,%5,%6,%7}, {%8,%9}, {%10,%11,%12,%13};"
        : "=f"(d[0]), "=f"(d[1]), "=f"(d[2]), "=f"(d[3])
        : "r"(a[0]), "r"(a[1]), "r"(a[2]), "r"(a[3]),
          "r"(b0), "r"(b1),
          "f"(c[0]), "f"(c[1]), "f"(c[2]), "f"(c[3]));
}

__device__ __forceinline__ void ldsm4(uint32_t* r, uint32_t addr) {
    asm volatile("ldmatrix.sync.aligned.m8n8.x4.shared.b16 {%0,%1,%2,%3}, [%4];"
                 : "=r"(r[0]), "=r"(r[1]), "=r"(r[2]), "=r"(r[3]) : "r"(addr));
}
__device__ __forceinline__ void ldsm4t(uint32_t* r, uint32_t addr) {
    asm volatile("ldmatrix.sync.aligned.m8n8.x4.trans.shared.b16 {%0,%1,%2,%3}, [%4];"
                 : "=r"(r[0]), "=r"(r[1]), "=r"(r[2]), "=r"(r[3]) : "r"(addr));
}

// ---------------------------------------------------------------------------
// Kernel 1: QKV projection (round-7 config: 256 thr, M tile 128).
// X[32768,256] @ [Wq|Wk|Wv][256,96] + bias, ReLU -> g_q/g_k/g_v (fp16).
// ---------------------------------------------------------------------------
__global__ void __launch_bounds__(256) qkv_kernel(
    const float* __restrict__ x,
    const float* __restrict__ Wq, const float* __restrict__ bq,
    const float* __restrict__ Wk, const float* __restrict__ bk,
    const float* __restrict__ Wv, const float* __restrict__ bv)
{
    __shared__ __half Xs[2][128 * TS];
    __shared__ __half Ws[2][32 * WQS];
    __shared__ float bsm[96];

    const int tid = threadIdx.x;
    const int warp = tid >> 5, lane = tid & 31;
    const int gid = lane >> 2, tig = lane & 3;
    const int row0 = blockIdx.x * 128;

    const uint32_t xs_base = (uint32_t)__cvta_generic_to_shared(&Xs[0][0]);
    const uint32_t ws_base = (uint32_t)__cvta_generic_to_shared(&Ws[0][0]);
    const uint32_t XBUF = 128 * TS * 2;
    const uint32_t WBUF = 32 * WQS * 2;

    if (tid < 96) bsm[tid] = (tid < 32) ? bq[tid] : (tid < 64 ? bk[tid - 32] : bv[tid - 64]);

    const float* wmat[3] = {Wq, Wk, Wv};

    float acc[12][4];
#pragma unroll
    for (int nb = 0; nb < 12; nb++)
#pragma unroll
        for (int r = 0; r < 4; r++) acc[nb][r] = 0.f;

    float4 xr[4], wr[3];
#pragma unroll
    for (int it = 0; it < 4; it++) {
        int i = tid + it * 256;
        int r = i >> 3, c4 = i & 7;
        xr[it] = *(const float4*)(x + (size_t)(row0 + r) * CIN + c4 * 4);
    }
#pragma unroll
    for (int m = 0; m < 3; m++) {
        int kk = tid >> 3, c4 = tid & 7;
        wr[m] = *(const float4*)(wmat[m] + (size_t)kk * DHEAD + c4 * 4);
    }
#pragma unroll
    for (int it = 0; it < 4; it++) {
        int i = tid + it * 256;
        int r = i >> 3, c4 = i & 7;
        uint2 p; p.x = pack2(xr[it].x, xr[it].y); p.y = pack2(xr[it].z, xr[it].w);
        *(uint2*)&Xs[0][r * TS + c4 * 4] = p;
    }
#pragma unroll
    for (int m = 0; m < 3; m++) {
        int kk = tid >> 3, c4 = tid & 7;
        uint2 p; p.x = pack2(wr[m].x, wr[m].y); p.y = pack2(wr[m].z, wr[m].w);
        *(uint2*)&Ws[0][kk * WQS + m * 32 + c4 * 4] = p;
    }
    __syncthreads();

    for (int c = 0; c < 8; c++) {
        const int cur = c & 1;

        if (c + 1 < 8) {
            int kc = (c + 1) * 32;
#pragma unroll
            for (int it = 0; it < 4; it++) {
                int i = tid + it * 256;
                int r = i >> 3, c4 = i & 7;
                xr[it] = *(const float4*)(x + (size_t)(row0 + r) * CIN + kc + c4 * 4);
            }
#pragma unroll
            for (int m = 0; m < 3; m++) {
                int kk = tid >> 3, c4 = tid & 7;
                wr[m] = *(const float4*)(wmat[m] + (size_t)(kc + kk) * DHEAD + c4 * 4);
            }
        }

        uint32_t a[2][4];
#pragma unroll
        for (int ks = 0; ks < 2; ks++) {
            uint32_t addr = xs_base + cur * XBUF +
                ((warp * 16 + ((lane >> 3) & 1) * 8 + (lane & 7)) * TS) * 2 +
                (ks * 16 + (lane >> 4) * 8) * 2;
            ldsm4(a[ks], addr);
        }
#pragma unroll
        for (int ks = 0; ks < 2; ks++) {
#pragma unroll
            for (int nbp = 0; nbp < 6; nbp++) {
                uint32_t wb[4];
                uint32_t addr = ws_base + cur * WBUF +
                    ((ks * 16 + ((lane >> 3) & 1) * 8 + (lane & 7)) * WQS) * 2 +
                    (nbp * 16 + (lane >> 4) * 8) * 2;
                ldsm4t(wb, addr);
                mma_f16(acc[2 * nbp],     a[ks], wb[0], wb[1], acc[2 * nbp]);
                mma_f16(acc[2 * nbp + 1], a[ks], wb[2], wb[3], acc[2 * nbp + 1]);
            }
        }

        if (c + 1 < 8) {
#pragma unroll
            for (int it = 0; it < 4; it++) {
                int i = tid + it * 256;
                int r = i >> 3, c4 = i & 7;
                uint2 p; p.x = pack2(xr[it].x, xr[it].y); p.y = pack2(xr[it].z, xr[it].w);
                *(uint2*)&Xs[cur ^ 1][r * TS + c4 * 4] = p;
            }
#pragma unroll
            for (int m = 0; m < 3; m++) {
                int kk = tid >> 3, c4 = tid & 7;
                uint2 p; p.x = pack2(wr[m].x, wr[m].y); p.y = pack2(wr[m].z, wr[m].w);
                *(uint2*)&Ws[cur ^ 1][kk * WQS + m * 32 + c4 * 4] = p;
            }
        }
        __syncthreads();
    }

#pragma unroll
    for (int nb = 0; nb < 12; nb++) {
        int cc = nb * 8 + 2 * tig;
        float b0 = bsm[cc], b1 = bsm[cc + 1];
        int r0 = row0 + warp * 16 + gid;
        __half* dst; int col;
        if (nb < 4)      { dst = g_q; col = cc; }
        else if (nb < 8) { dst = g_k; col = cc - 32; }
        else             { dst = g_v; col = cc - 64; }
        *(uint32_t*)(dst + (size_t)r0 * DHEAD + col) =
            pack2(fmaxf(acc[nb][0] + b0, 0.f), fmaxf(acc[nb][1] + b1, 0.f));
        *(uint32_t*)(dst + (size_t)(r0 + 8) * DHEAD + col) =
            pack2(fmaxf(acc[nb][2] + b0, 0.f), fmaxf(acc[nb][3] + b1, 0.f));
    }
}

// ---------------------------------------------------------------------------
// Kernel 2: flash attention.
//  - fp16 mma, ldmatrix, zero-copy P, ex2.approx.f16x2
//  - NO l-mma at all: per-thread fp32 l partials via off-path HADD2 tree;
//    cross-lane reduce deferred to the epilogue (2 shfl, once).
// Grid (32, 8), 8 warps, double-buffered K/V. 32 mmas/tile.
// ---------------------------------------------------------------------------
__global__ void __launch_bounds__(256, 2) attn_kernel()
{
    __shared__ __half Ks[2][MT * TS];
    __shared__ __half Vs[2][MT * TS];

    const int b   = blockIdx.y;
    const int qt  = blockIdx.x;
    const int tid = threadIdx.x;
    const int warp = tid >> 5, lane = tid & 31;
    const int gid = lane >> 2, tig = lane & 3;

    const uint32_t ks_base = (uint32_t)__cvta_generic_to_shared(&Ks[0][0]);
    const uint32_t vs_base = (uint32_t)__cvta_generic_to_shared(&Vs[0][0]);
    const uint32_t BUF = MT * TS * 2;

    const __half* qg = g_q + ((size_t)b * NPIX + (size_t)qt * QT + warp * 16) * DHEAD;
    const __half* kg = g_k + (size_t)b * NPIX * DHEAD;
    const __half* vg = g_v + (size_t)b * NPIX * DHEAD;

    uint32_t qa[2][4];
#pragma unroll
    for (int ks = 0; ks < 2; ks++) {
        qa[ks][0] = *(const uint32_t*)(qg + (size_t)(gid)     * DHEAD + ks * 16 + 2 * tig);
        qa[ks][1] = *(const uint32_t*)(qg + (size_t)(gid + 8) * DHEAD + ks * 16 + 2 * tig);
        qa[ks][2] = *(const uint32_t*)(qg + (size_t)(gid)     * DHEAD + ks * 16 + 8 + 2 * tig);
        qa[ks][3] = *(const uint32_t*)(qg + (size_t)(gid + 8) * DHEAD + ks * 16 + 8 + 2 * tig);
    }

    float O[4][4];
#pragma unroll
    for (int nb = 0; nb < 4; nb++)
#pragma unroll
        for (int r = 0; r < 4; r++) O[nb][r] = 0.f;
    float mi0 = -1e30f, mi1 = -1e30f;
    float lsum0 = 0.f, lsum1 = 0.f;     // per-thread l partials (16 cols each)

    const int sr = tid >> 2, sc = (tid & 3) * 8;
    uint4 kpre, vpre;
    kpre = *(const uint4*)(kg + (size_t)sr * DHEAD + sc);
    vpre = *(const uint4*)(vg + (size_t)sr * DHEAD + sc);
    *(uint4*)&Ks[0][sr * TS + sc] = kpre;
    *(uint4*)&Vs[0][sr * TS + sc] = vpre;
    __syncthreads();

    for (int mt = 0; mt < NPIX / MT; mt++) {
        const int cur = mt & 1;

        if (mt + 1 < NPIX / MT) {
            kpre = *(const uint4*)(kg + (size_t)((mt + 1) * MT + sr) * DHEAD + sc);
            vpre = *(const uint4*)(vg + (size_t)((mt + 1) * MT + sr) * DHEAD + sc);
        }

        // ---- mma1: S(16x64) = Q K^T ----
        float S[8][4];
#pragma unroll
        for (int nb = 0; nb < 8; nb++) {
#pragma unroll
            for (int r = 0; r < 4; r++) S[nb][r] = 0.f;
            uint32_t kb[4];
            uint32_t addr = ks_base + cur * BUF +
                ((nb * 8 + (lane & 7)) * TS) * 2 + (lane >> 3) * 16;
            ldsm4(kb, addr);
            mma_f16(S[nb], qa[0], kb[0], kb[1], S[nb]);
            mma_f16(S[nb], qa[1], kb[2], kb[3], S[nb]);
        }

        // ---- online softmax (rows gid, gid+8) ----
        float rm0 = -1e30f, rm1 = -1e30f;
#pragma unroll
        for (int nb = 0; nb < 8; nb++) {
            rm0 = fmaxf(rm0, fmaxf(S[nb][0], S[nb][1]));
            rm1 = fmaxf(rm1, fmaxf(S[nb][2], S[nb][3]));
        }
        rm0 = fmaxf(rm0, __shfl_xor_sync(0xffffffffu, rm0, 1));
        rm0 = fmaxf(rm0, __shfl_xor_sync(0xffffffffu, rm0, 2));
        rm1 = fmaxf(rm1, __shfl_xor_sync(0xffffffffu, rm1, 1));
        rm1 = fmaxf(rm1, __shfl_xor_sync(0xffffffffu, rm1, 2));

        float nm0 = fmaxf(mi0, rm0), nm1 = fmaxf(mi1, rm1);
        float corr0 = exp2f((mi0 - nm0) * LOG2E);
        float corr1 = exp2f((mi1 - nm1) * LOG2E);
        mi0 = nm0; mi1 = nm1;
        const float nc0 = nm0 * (-LOG2E), nc1 = nm1 * (-LOG2E);

        // exp in fp16x2, pack directly into mma2 A-fragments (1 FFMA/elem)
        uint32_t P[4][4];
#pragma unroll
        for (int nb = 0; nb < 8; nb++) {
            float u0 = fmaf(S[nb][0], LOG2E, nc0);
            float u1 = fmaf(S[nb][1], LOG2E, nc0);
            float u2 = fmaf(S[nb][2], LOG2E, nc1);
            float u3 = fmaf(S[nb][3], LOG2E, nc1);
            int ks2 = nb >> 1, hi = (nb & 1) * 2;
            P[ks2][hi]     = h2exp2(pack2(u0, u1));
            P[ks2][hi + 1] = h2exp2(pack2(u2, u3));
        }

        // rescale O
#pragma unroll
        for (int nb = 0; nb < 4; nb++) {
            O[nb][0] *= corr0; O[nb][1] *= corr0;
            O[nb][2] *= corr1; O[nb][3] *= corr1;
        }

        // ---- mma2: O(16x32) += P V ----
#pragma unroll
        for (int ks2 = 0; ks2 < 4; ks2++) {
            const uint32_t* a = P[ks2];
#pragma unroll
            for (int dbp = 0; dbp < 2; dbp++) {
                uint32_t vb[4];
                uint32_t addr = vs_base + cur * BUF +
                    ((ks2 * 16 + ((lane >> 3) & 1) * 8 + (lane & 7)) * TS) * 2 +
                    dbp * 32 + (lane >> 4) * 16;
                ldsm4t(vb, addr);
                mma_f16(O[2 * dbp],     a, vb[0], vb[1], O[2 * dbp]);
                mma_f16(O[2 * dbp + 1], a, vb[2], vb[3], O[2 * dbp + 1]);
            }
        }

        // ---- l partials: off-path HADD2 trees, accumulated in fp32 ----
        {
            uint32_t t0 = hadd2u(hadd2u(P[0][0], P[1][0]), hadd2u(P[2][0], P[3][0]));
            uint32_t t1 = hadd2u(hadd2u(P[0][2], P[1][2]), hadd2u(P[2][2], P[3][2]));
            uint32_t t2 = hadd2u(hadd2u(P[0][1], P[1][1]), hadd2u(P[2][1], P[3][1]));
            uint32_t t3 = hadd2u(hadd2u(P[0][3], P[1][3]), hadd2u(P[2][3], P[3][3]));
            lsum0 = lsum0 * corr0 + hsum2f(t0) + hsum2f(t1);   // row gid
            lsum1 = lsum1 * corr1 + hsum2f(t2) + hsum2f(t3);   // row gid+8
        }

        if (mt + 1 < NPIX / MT) {
            *(uint4*)&Ks[cur ^ 1][sr * TS + sc] = kpre;
            *(uint4*)&Vs[cur ^ 1][sr * TS + sc] = vpre;
        }
        __syncthreads();
    }

    // epilogue: quad-reduce l (once), divide, fp16 store
    lsum0 += __shfl_xor_sync(0xffffffffu, lsum0, 1);
    lsum0 += __shfl_xor_sync(0xffffffffu, lsum0, 2);
    lsum1 += __shfl_xor_sync(0xffffffffu, lsum1, 1);
    lsum1 += __shfl_xor_sync(0xffffffffu, lsum1, 2);
    float inv0 = 1.f / lsum0, inv1 = 1.f / lsum1;
    size_t base = (size_t)b * NPIX + (size_t)qt * QT + warp * 16;
#pragma unroll
    for (int db = 0; db < 4; db++) {
        *(uint32_t*)(g_attn + (base + gid) * DHEAD + db * 8 + 2 * tig) =
            pack2(O[db][0] * inv0, O[db][1] * inv0);
        *(uint32_t*)(g_attn + (base + gid + 8) * DHEAD + db * 8 + 2 * tig) =
            pack2(O[db][2] * inv1, O[db][3] * inv1);
    }
}

// ---------------------------------------------------------------------------
// Kernel 3: output projection (round-7 config: 256 thr, 128-row tiles).
// ---------------------------------------------------------------------------
__global__ void __launch_bounds__(256) proj_kernel(
    const float* __restrict__ Wo,
    const float* __restrict__ bo,
    float* __restrict__ out)
{
    __shared__ __half As[128 * TS];
    __shared__ __half Wos[32 * WOS];
    __shared__ float bos[128];

    const int tid = threadIdx.x;
    const int warp = tid >> 5, lane = tid & 31;
    const int gid = lane >> 2, tig = lane & 3;
    const int row0 = blockIdx.x * 128;
    const int n0   = blockIdx.y * 128;

    const uint32_t as_base = (uint32_t)__cvta_generic_to_shared(&As[0]);
    const uint32_t wo_base = (uint32_t)__cvta_generic_to_shared(&Wos[0]);

    if (tid < 128) bos[tid] = bo[n0 + tid];

#pragma unroll
    for (int it = 0; it < 2; it++) {
        int i = tid + it * 256;
        int r = i >> 2, c8 = (i & 3) * 8;
        *(uint4*)&As[r * TS + c8] =
            *(const uint4*)(g_attn + (size_t)(row0 + r) * DHEAD + c8);
    }
#pragma unroll
    for (int it = 0; it < 4; it++) {
        int i = tid + it * 256;
        int kk = i >> 5, c4 = i & 31;
        float4 v = *(const float4*)(Wo + (size_t)kk * CIN + n0 + c4 * 4);
        uint2 p; p.x = pack2(v.x, v.y); p.y = pack2(v.z, v.w);
        *(uint2*)&Wos[kk * WOS + c4 * 4] = p;
    }
    __syncthreads();

    float acc[16][4];
#pragma unroll
    for (int nb = 0; nb < 16; nb++)
#pragma unroll
        for (int r = 0; r < 4; r++) acc[nb][r] = 0.f;

    uint32_t a[2][4];
#pragma unroll
    for (int ks = 0; ks < 2; ks++) {
        uint32_t addr = as_base +
            ((warp * 16 + ((lane >> 3) & 1) * 8 + (lane & 7)) * TS) * 2 +
            (ks * 16 + (lane >> 4) * 8) * 2;
        ldsm4(a[ks], addr);
    }
#pragma unroll
    for (int ks = 0; ks < 2; ks++) {
#pragma unroll
        for (int nbp = 0; nbp < 8; nbp++) {
            uint32_t wb[4];
            uint32_t addr = wo_base +
                ((ks * 16 + ((lane >> 3) & 1) * 8 + (lane & 7)) * WOS) * 2 +
                (nbp * 16 + (lane >> 4) * 8) * 2;
            ldsm4t(wb, addr);
            mma_f16(acc[2 * nbp],     a[ks], wb[0], wb[1], acc[2 * nbp]);
            mma_f16(acc[2 * nbp + 1], a[ks], wb[2], wb[3], acc[2 * nbp + 1]);
        }
    }

#pragma unroll
    for (int nb = 0; nb < 16; nb++) {
        int cc = nb * 8 + 2 * tig;
        float b0 = bos[cc], b1 = bos[cc + 1];
        int r0 = row0 + warp * 16 + gid;
        float2 lo, hi;
        lo.x = fmaxf(acc[nb][0] + b0, 0.f); lo.y = fmaxf(acc[nb][1] + b1, 0.f);
        hi.x = fmaxf(acc[nb][2] + b0, 0.f); hi.y = fmaxf(acc[nb][3] + b1, 0.f);
        *(float2*)(out + (size_t)r0 * CIN + n0 + cc)       = lo;
        *(float2*)(out + (size_t)(r0 + 8) * CIN + n0 + cc) = hi;
    }
}

// ---------------------------------------------------------------------------
extern "C" void kernel_launch(void* const* d_in, const int* in_sizes, int n_in,
                              void* d_out, int out_size)
{
    const float* x  = (const float*)d_in[0];
    const float* Wq = (const float*)d_in[1];
    const float* bq = (const float*)d_in[2];
    const float* Wk = (const float*)d_in[3];
    const float* bk = (const float*)d_in[4];
    const float* Wv = (const float*)d_in[5];
    const float* bv = (const float*)d_in[6];
    const float* Wo = (const float*)d_in[7];
    const float* bo = (const float*)d_in[8];
    float* out = (float*)d_out;

    qkv_kernel<<<MROWS / 128, 256>>>(x, Wq, bq, Wk, bk, Wv, bv);
    attn_kernel<<<dim3(NPIX / QT, BATCH), 256>>>();
    proj_kernel<<<dim3(MROWS / 128, 2), 256>>>(Wo, bo, out);
}

// round 13
// speedup vs baseline: 1.0877x; 1.0877x over previous
#include <cuda_runtime.h>
#include <cuda_fp16.h>
#include <cstdint>

// Problem constants
#define BATCH 8
#define NPIX  4096          // 64*64
#define CIN   256
#define DHEAD 32
#define MROWS (BATCH*NPIX)  // 32768

#define QT 128              // q rows per attn block (8 warps x 16 rows)
#define MT 64               // k/v rows per inner tile

// smem strides (in halves). 40 halves = 80B rows: 16B aligned.
#define TS 40
#define WQS 104
#define WOS2 264            // Wo tile stride: 256+8 halves; 528B rows = 33*16B

#define LOG2E 1.4426950408889634f

// fp16 scratch (device globals; no runtime allocation allowed)
__device__ __half g_q[MROWS * DHEAD];
__device__ __half g_k[MROWS * DHEAD];
__device__ __half g_v[MROWS * DHEAD];

// ---------------------------------------------------------------------------
// helpers
// ---------------------------------------------------------------------------
__device__ __forceinline__ uint32_t pack2(float lo, float hi) {
    __half2 h = __floats2half2_rn(lo, hi);
    return *reinterpret_cast<uint32_t*>(&h);
}
__device__ __forceinline__ uint32_t h2exp2(uint32_t u) {
    uint32_t r;
    asm("ex2.approx.f16x2 %0, %1;" : "=r"(r) : "r"(u));
    return r;
}

__device__ __forceinline__ void mma_f16(float* d, const uint32_t* a,
                                        uint32_t b0, uint32_t b1, const float* c)
{
    asm("mma.sync.aligned.m16n8k16.row.col.f32.f16.f16.f32 "
        "{%0,%1,%2,%3}, {%4,%5,%6,%7}, {%8,%9}, {%10,%11,%12,%13};"
        : "=f"(d[0]), "=f"(d[1]), "=f"(d[2]), "=f"(d[3])
        : "r"(a[0]), "r"(a[1]), "r"(a[2]), "r"(a[3]),
          "r"(b0), "r"(b1),
          "f"(c[0]), "f"(c[1]), "f"(c[2]), "f"(c[3]));
}

__device__ __forceinline__ void ldsm4(uint32_t* r, uint32_t addr) {
    asm volatile("ldmatrix.sync.aligned.m8n8.x4.shared.b16 {%0,%1,%2,%3}, [%4];"
                 : "=r"(r[0]), "=r"(r[1]), "=r"(r[2]), "=r"(r[3]) : "r"(addr));
}
__device__ __forceinline__ void ldsm4t(uint32_t* r, uint32_t addr) {
    asm volatile("ldmatrix.sync.aligned.m8n8.x4.trans.shared.b16 {%0,%1,%2,%3}, [%4];"
                 : "=r"(r[0]), "=r"(r[1]), "=r"(r[2]), "=r"(r[3]) : "r"(addr));
}

// ---------------------------------------------------------------------------
// Kernel 1: QKV projection (round-7 config, unchanged: 256 thr, M tile 128).
// X[32768,256] @ [Wq|Wk|Wv][256,96] + bias, ReLU -> g_q/g_k/g_v (fp16).
// ---------------------------------------------------------------------------
__global__ void __launch_bounds__(256) qkv_kernel(
    const float* __restrict__ x,
    const float* __restrict__ Wq, const float* __restrict__ bq,
    const float* __restrict__ Wk, const float* __restrict__ bk,
    const float* __restrict__ Wv, const float* __restrict__ bv)
{
    __shared__ __half Xs[2][128 * TS];
    __shared__ __half Ws[2][32 * WQS];
    __shared__ float bsm[96];

    const int tid = threadIdx.x;
    const int warp = tid >> 5, lane = tid & 31;
    const int gid = lane >> 2, tig = lane & 3;
    const int row0 = blockIdx.x * 128;

    const uint32_t xs_base = (uint32_t)__cvta_generic_to_shared(&Xs[0][0]);
    const uint32_t ws_base = (uint32_t)__cvta_generic_to_shared(&Ws[0][0]);
    const uint32_t XBUF = 128 * TS * 2;
    const uint32_t WBUF = 32 * WQS * 2;

    if (tid < 96) bsm[tid] = (tid < 32) ? bq[tid] : (tid < 64 ? bk[tid - 32] : bv[tid - 64]);

    const float* wmat[3] = {Wq, Wk, Wv};

    float acc[12][4];
#pragma unroll
    for (int nb = 0; nb < 12; nb++)
#pragma unroll
        for (int r = 0; r < 4; r++) acc[nb][r] = 0.f;

    float4 xr[4], wr[3];
#pragma unroll
    for (int it = 0; it < 4; it++) {
        int i = tid + it * 256;
        int r = i >> 3, c4 = i & 7;
        xr[it] = *(const float4*)(x + (size_t)(row0 + r) * CIN + c4 * 4);
    }
#pragma unroll
    for (int m = 0; m < 3; m++) {
        int kk = tid >> 3, c4 = tid & 7;
        wr[m] = *(const float4*)(wmat[m] + (size_t)kk * DHEAD + c4 * 4);
    }
#pragma unroll
    for (int it = 0; it < 4; it++) {
        int i = tid + it * 256;
        int r = i >> 3, c4 = i & 7;
        uint2 p; p.x = pack2(xr[it].x, xr[it].y); p.y = pack2(xr[it].z, xr[it].w);
        *(uint2*)&Xs[0][r * TS + c4 * 4] = p;
    }
#pragma unroll
    for (int m = 0; m < 3; m++) {
        int kk = tid >> 3, c4 = tid & 7;
        uint2 p; p.x = pack2(wr[m].x, wr[m].y); p.y = pack2(wr[m].z, wr[m].w);
        *(uint2*)&Ws[0][kk * WQS + m * 32 + c4 * 4] = p;
    }
    __syncthreads();

    for (int c = 0; c < 8; c++) {
        const int cur = c & 1;

        if (c + 1 < 8) {
            int kc = (c + 1) * 32;
#pragma unroll
            for (int it = 0; it < 4; it++) {
                int i = tid + it * 256;
                int r = i >> 3, c4 = i & 7;
                xr[it] = *(const float4*)(x + (size_t)(row0 + r) * CIN + kc + c4 * 4);
            }
#pragma unroll
            for (int m = 0; m < 3; m++) {
                int kk = tid >> 3, c4 = tid & 7;
                wr[m] = *(const float4*)(wmat[m] + (size_t)(kc + kk) * DHEAD + c4 * 4);
            }
        }

        uint32_t a[2][4];
#pragma unroll
        for (int ks = 0; ks < 2; ks++) {
            uint32_t addr = xs_base + cur * XBUF +
                ((warp * 16 + ((lane >> 3) & 1) * 8 + (lane & 7)) * TS) * 2 +
                (ks * 16 + (lane >> 4) * 8) * 2;
            ldsm4(a[ks], addr);
        }
#pragma unroll
        for (int ks = 0; ks < 2; ks++) {
#pragma unroll
            for (int nbp = 0; nbp < 6; nbp++) {
                uint32_t wb[4];
                uint32_t addr = ws_base + cur * WBUF +
                    ((ks * 16 + ((lane >> 3) & 1) * 8 + (lane & 7)) * WQS) * 2 +
                    (nbp * 16 + (lane >> 4) * 8) * 2;
                ldsm4t(wb, addr);
                mma_f16(acc[2 * nbp],     a[ks], wb[0], wb[1], acc[2 * nbp]);
                mma_f16(acc[2 * nbp + 1], a[ks], wb[2], wb[3], acc[2 * nbp + 1]);
            }
        }

        if (c + 1 < 8) {
#pragma unroll
            for (int it = 0; it < 4; it++) {
                int i = tid + it * 256;
                int r = i >> 3, c4 = i & 7;
                uint2 p; p.x = pack2(xr[it].x, xr[it].y); p.y = pack2(xr[it].z, xr[it].w);
                *(uint2*)&Xs[cur ^ 1][r * TS + c4 * 4] = p;
            }
#pragma unroll
            for (int m = 0; m < 3; m++) {
                int kk = tid >> 3, c4 = tid & 7;
                uint2 p; p.x = pack2(wr[m].x, wr[m].y); p.y = pack2(wr[m].z, wr[m].w);
                *(uint2*)&Ws[cur ^ 1][kk * WQS + m * 32 + c4 * 4] = p;
            }
        }
        __syncthreads();
    }

#pragma unroll
    for (int nb = 0; nb < 12; nb++) {
        int cc = nb * 8 + 2 * tig;
        float b0 = bsm[cc], b1 = bsm[cc + 1];
        int r0 = row0 + warp * 16 + gid;
        __half* dst; int col;
        if (nb < 4)      { dst = g_q; col = cc; }
        else if (nb < 8) { dst = g_k; col = cc - 32; }
        else             { dst = g_v; col = cc - 64; }
        *(uint32_t*)(dst + (size_t)r0 * DHEAD + col) =
            pack2(fmaxf(acc[nb][0] + b0, 0.f), fmaxf(acc[nb][1] + b1, 0.f));
        *(uint32_t*)(dst + (size_t)(r0 + 8) * DHEAD + col) =
            pack2(fmaxf(acc[nb][2] + b0, 0.f), fmaxf(acc[nb][3] + b1, 0.f));
    }
}

// ---------------------------------------------------------------------------
// Kernel 2: flash attention + FUSED output projection.
//  Mainloop: exact round-7 structure (best measured): fp16 mma, ldmatrix,
//  zero-copy P, ex2.approx.f16x2, l via 4 ones-mmas.
//  Epilogue: O*inv is ALREADY the A-fragment of the proj GEMM -> 64 mmas/warp
//  against smem-resident Wo, bias+ReLU, fp32 store. No g_attn, no 3rd kernel.
// Grid (32, 8), 8 warps, double-buffered K/V.
// ---------------------------------------------------------------------------
__global__ void __launch_bounds__(256, 2) attn_kernel(
    const float* __restrict__ Wo,
    const float* __restrict__ bo,
    float* __restrict__ out)
{
    __shared__ __half Ks[2][MT * TS];      // 2 x 5 KB
    __shared__ __half Vs[2][MT * TS];      // 2 x 5 KB
    __shared__ __half Wos[32 * WOS2];      // 16.5 KB
    __shared__ float bos[256];

    const int b   = blockIdx.y;
    const int qt  = blockIdx.x;
    const int tid = threadIdx.x;
    const int warp = tid >> 5, lane = tid & 31;
    const int gid = lane >> 2, tig = lane & 3;

    const uint32_t ks_base = (uint32_t)__cvta_generic_to_shared(&Ks[0][0]);
    const uint32_t vs_base = (uint32_t)__cvta_generic_to_shared(&Vs[0][0]);
    const uint32_t wo_base = (uint32_t)__cvta_generic_to_shared(&Wos[0]);
    const uint32_t BUF = MT * TS * 2;

    // constant ones B-frag for the l accumulator column
    const uint32_t ones = (gid == 0) ? 0x3C003C00u : 0u;

    const __half* qg = g_q + ((size_t)b * NPIX + (size_t)qt * QT + warp * 16) * DHEAD;
    const __half* kg = g_k + (size_t)b * NPIX * DHEAD;
    const __half* vg = g_v + (size_t)b * NPIX * DHEAD;

    // ---- prologue: Wo -> smem (fp16), bias -> smem (one-time) ----
    bos[tid] = bo[tid];
#pragma unroll
    for (int it = 0; it < 8; it++) {
        int i = tid + it * 256;            // 0..2047 float4s
        int kk = i >> 6, c4 = i & 63;
        float4 v = *(const float4*)(Wo + (size_t)kk * CIN + c4 * 4);
        uint2 p; p.x = pack2(v.x, v.y); p.y = pack2(v.z, v.w);
        *(uint2*)&Wos[kk * WOS2 + c4 * 4] = p;
    }

    uint32_t qa[2][4];
#pragma unroll
    for (int ks = 0; ks < 2; ks++) {
        qa[ks][0] = *(const uint32_t*)(qg + (size_t)(gid)     * DHEAD + ks * 16 + 2 * tig);
        qa[ks][1] = *(const uint32_t*)(qg + (size_t)(gid + 8) * DHEAD + ks * 16 + 2 * tig);
        qa[ks][2] = *(const uint32_t*)(qg + (size_t)(gid)     * DHEAD + ks * 16 + 8 + 2 * tig);
        qa[ks][3] = *(const uint32_t*)(qg + (size_t)(gid + 8) * DHEAD + ks * 16 + 8 + 2 * tig);
    }

    // O[0..3] = output d-blocks, O[4] = l (row-sum) block
    float O[5][4];
#pragma unroll
    for (int nb = 0; nb < 5; nb++)
#pragma unroll
        for (int r = 0; r < 4; r++) O[nb][r] = 0.f;
    float mi0 = -1e30f, mi1 = -1e30f;

    const int sr = tid >> 2, sc = (tid & 3) * 8;
    uint4 kpre, vpre;
    kpre = *(const uint4*)(kg + (size_t)sr * DHEAD + sc);
    vpre = *(const uint4*)(vg + (size_t)sr * DHEAD + sc);
    *(uint4*)&Ks[0][sr * TS + sc] = kpre;
    *(uint4*)&Vs[0][sr * TS + sc] = vpre;
    __syncthreads();

    for (int mt = 0; mt < NPIX / MT; mt++) {
        const int cur = mt & 1;

        if (mt + 1 < NPIX / MT) {
            kpre = *(const uint4*)(kg + (size_t)((mt + 1) * MT + sr) * DHEAD + sc);
            vpre = *(const uint4*)(vg + (size_t)((mt + 1) * MT + sr) * DHEAD + sc);
        }

        // ---- mma1: S(16x64) = Q K^T ----
        float S[8][4];
#pragma unroll
        for (int nb = 0; nb < 8; nb++) {
#pragma unroll
            for (int r = 0; r < 4; r++) S[nb][r] = 0.f;
            uint32_t kb[4];
            uint32_t addr = ks_base + cur * BUF +
                ((nb * 8 + (lane & 7)) * TS) * 2 + (lane >> 3) * 16;
            ldsm4(kb, addr);
            mma_f16(S[nb], qa[0], kb[0], kb[1], S[nb]);
            mma_f16(S[nb], qa[1], kb[2], kb[3], S[nb]);
        }

        // ---- online softmax (rows gid, gid+8) ----
        float rm0 = -1e30f, rm1 = -1e30f;
#pragma unroll
        for (int nb = 0; nb < 8; nb++) {
            rm0 = fmaxf(rm0, fmaxf(S[nb][0], S[nb][1]));
            rm1 = fmaxf(rm1, fmaxf(S[nb][2], S[nb][3]));
        }
        rm0 = fmaxf(rm0, __shfl_xor_sync(0xffffffffu, rm0, 1));
        rm0 = fmaxf(rm0, __shfl_xor_sync(0xffffffffu, rm0, 2));
        rm1 = fmaxf(rm1, __shfl_xor_sync(0xffffffffu, rm1, 1));
        rm1 = fmaxf(rm1, __shfl_xor_sync(0xffffffffu, rm1, 2));

        float nm0 = fmaxf(mi0, rm0), nm1 = fmaxf(mi1, rm1);
        float corr0 = exp2f((mi0 - nm0) * LOG2E);
        float corr1 = exp2f((mi1 - nm1) * LOG2E);
        mi0 = nm0; mi1 = nm1;
        const float nc0 = nm0 * (-LOG2E), nc1 = nm1 * (-LOG2E);

        // exp in fp16x2, pack directly into mma2 A-fragments (1 FFMA/elem)
        uint32_t P[4][4];
#pragma unroll
        for (int nb = 0; nb < 8; nb++) {
            float u0 = fmaf(S[nb][0], LOG2E, nc0);
            float u1 = fmaf(S[nb][1], LOG2E, nc0);
            float u2 = fmaf(S[nb][2], LOG2E, nc1);
            float u3 = fmaf(S[nb][3], LOG2E, nc1);
            int ks2 = nb >> 1, hi = (nb & 1) * 2;
            P[ks2][hi]     = h2exp2(pack2(u0, u1));
            P[ks2][hi + 1] = h2exp2(pack2(u2, u3));
        }

        // rescale O (incl. l block)
#pragma unroll
        for (int nb = 0; nb < 5; nb++) {
            O[nb][0] *= corr0; O[nb][1] *= corr0;
            O[nb][2] *= corr1; O[nb][3] *= corr1;
        }

        // ---- mma2: O(16x32) += P V ;  l += P @ ones ----
#pragma unroll
        for (int ks2 = 0; ks2 < 4; ks2++) {
            const uint32_t* a = P[ks2];
#pragma unroll
            for (int dbp = 0; dbp < 2; dbp++) {
                uint32_t vb[4];
                uint32_t addr = vs_base + cur * BUF +
                    ((ks2 * 16 + ((lane >> 3) & 1) * 8 + (lane & 7)) * TS) * 2 +
                    dbp * 32 + (lane >> 4) * 16;
                ldsm4t(vb, addr);
                mma_f16(O[2 * dbp],     a, vb[0], vb[1], O[2 * dbp]);
                mma_f16(O[2 * dbp + 1], a, vb[2], vb[3], O[2 * dbp + 1]);
            }
            mma_f16(O[4], a, ones, ones, O[4]);
        }

        if (mt + 1 < NPIX / MT) {
            *(uint4*)&Ks[cur ^ 1][sr * TS + sc] = kpre;
            *(uint4*)&Vs[cur ^ 1][sr * TS + sc] = vpre;
        }
        __syncthreads();
    }

    // ---- fused epilogue: out = ReLU((O/l) @ Wo + bo) ----
    float l0 = __shfl_sync(0xffffffffu, O[4][0], lane & 28);
    float l1 = __shfl_sync(0xffffffffu, O[4][2], lane & 28);
    float inv0 = 1.f / l0, inv1 = 1.f / l1;

    // Pack normalized O into proj A-fragments: aep[ks] covers k-cols 16ks..16ks+15.
    uint32_t aep[2][4];
#pragma unroll
    for (int ks = 0; ks < 2; ks++) {
        aep[ks][0] = pack2(O[2 * ks][0] * inv0, O[2 * ks][1] * inv0);
        aep[ks][1] = pack2(O[2 * ks][2] * inv1, O[2 * ks][3] * inv1);
        aep[ks][2] = pack2(O[2 * ks + 1][0] * inv0, O[2 * ks + 1][1] * inv0);
        aep[ks][3] = pack2(O[2 * ks + 1][2] * inv1, O[2 * ks + 1][3] * inv1);
    }

    const size_t base = (size_t)b * NPIX + (size_t)qt * QT + warp * 16;
#pragma unroll
    for (int h = 0; h < 2; h++) {          // two 128-col halves (bounds regs)
        float acc[16][4];
#pragma unroll
        for (int nb = 0; nb < 16; nb++)
#pragma unroll
            for (int r = 0; r < 4; r++) acc[nb][r] = 0.f;

#pragma unroll
        for (int ks = 0; ks < 2; ks++) {
#pragma unroll
            for (int nbp = 0; nbp < 8; nbp++) {
                uint32_t wb[4];
                uint32_t addr = wo_base +
                    ((ks * 16 + ((lane >> 3) & 1) * 8 + (lane & 7)) * WOS2) * 2 +
                    (h * 128 + nbp * 16 + (lane >> 4) * 8) * 2;
                ldsm4t(wb, addr);
                mma_f16(acc[2 * nbp],     aep[ks], wb[0], wb[1], acc[2 * nbp]);
                mma_f16(acc[2 * nbp + 1], aep[ks], wb[2], wb[3], acc[2 * nbp + 1]);
            }
        }

#pragma unroll
        for (int nb = 0; nb < 16; nb++) {
            int cc = h * 128 + nb * 8 + 2 * tig;
            float b0 = bos[cc], b1 = bos[cc + 1];
            float2 lo, hi;
            lo.x = fmaxf(acc[nb][0] + b0, 0.f); lo.y = fmaxf(acc[nb][1] + b1, 0.f);
            hi.x = fmaxf(acc[nb][2] + b0, 0.f); hi.y = fmaxf(acc[nb][3] + b1, 0.f);
            *(float2*)(out + (base + gid) * CIN + cc)     = lo;
            *(float2*)(out + (base + gid + 8) * CIN + cc) = hi;
        }
    }
}

// ---------------------------------------------------------------------------
extern "C" void kernel_launch(void* const* d_in, const int* in_sizes, int n_in,
                              void* d_out, int out_size)
{
    const float* x  = (const float*)d_in[0];
    const float* Wq = (const float*)d_in[1];
    const float* bq = (const float*)d_in[2];
    const float* Wk = (const float*)d_in[3];
    const float* bk = (const float*)d_in[4];
    const float* Wv = (const float*)d_in[5];
    const float* bv = (const float*)d_in[6];
    const float* Wo = (const float*)d_in[7];
    const float* bo = (const float*)d_in[8];
    float* out = (float*)d_out;

    qkv_kernel<<<MROWS / 128, 256>>>(x, Wq, bq, Wk, bk, Wv, bv);
    attn_kernel<<<dim3(NPIX / QT, BATCH), 256>>>(Wo, bo, out);
}